// round 6
// baseline (speedup 1.0000x reference)
#include <cuda_runtime.h>
#include <cuda_fp16.h>

#define TT   1000
#define NCH  4096

// scratch (no cudaMalloc allowed)
__device__ float g_seq[NCH * TT];     // LSTM input, [chain][t], 16 MB
__device__ float g_feat[NCH * 32];    // [chain][ h_fwd(16) | h_bwd(16) ]

__device__ __forceinline__ float ex2f(float x) {
    float r; asm("ex2.approx.f32 %0, %1;" : "=f"(r) : "f"(x)); return r;
}
__device__ __forceinline__ float rcpf(float x) {
    float r; asm("rcp.approx.f32 %0, %1;" : "=f"(r) : "f"(x)); return r;
}

// FMA-pipe exp2: rint magic reduction + degree-6 Taylor on the fraction.
// Valid (and clamped) for |x| <= 60; rel err ~1.2e-7.
__device__ __forceinline__ float exp2_poly(float x) {
    x = fminf(fmaxf(x, -60.0f), 60.0f);
    const float MAGIC = 12582912.0f;              // 1.5 * 2^23
    const float tbig  = x + MAGIC;
    const float fi    = tbig - MAGIC;             // rint(x)
    const float f     = x - fi;                   // [-0.5, 0.5]
    const int   ii    = __float_as_int(tbig) - __float_as_int(MAGIC);
    const float sc    = __int_as_float((ii + 127) << 23);   // 2^ii
    const float u     = f * 0.6931471805599453f;
    float p = fmaf(u, 1.3888889e-3f, 8.3333333e-3f);
    p = fmaf(p, u, 4.1666667e-2f);
    p = fmaf(p, u, 1.6666667e-1f);
    p = fmaf(p, u, 0.5f);
    p = fmaf(p, u, 1.0f);
    p = fmaf(p, u, 1.0f);                         // 2^f
    return p * sc;
}

// LSTM cell update with minimal MUFU: 4 MUFU ex2-path + 2 MUFU rcp-path
//   sigmoid(x) = 1/(1 + 2^(-x*log2e));  tanh(x) = 2/(1 + 2^(-2x*log2e)) - 1
// Gate reciprocals batched via one rcp (Montgomery); tanh(g) ex2 on FMA pipe.
__device__ __forceinline__ void lstm_act(float gi, float gf, float gg, float go,
                                         float& c, float& h) {
    const float NL2E  = -1.4426950408889634f;
    const float N2L2E = -2.8853900817779268f;
    const float ei = ex2f(gi * NL2E);             // MUFU
    const float ef = ex2f(gf * NL2E);             // MUFU
    const float eo = ex2f(go * NL2E);             // MUFU
    const float eg = exp2_poly(gg * N2L2E);       // FMA pipe
    const float di = 1.0f + ei, df = 1.0f + ef, dg = 1.0f + eg, dd = 1.0f + eo;
    const float p1 = di * df;
    const float p2 = p1 * dg;
    const float p3 = p2 * dd;
    const float r  = rcpf(p3);                    // MUFU (1 rcp for 4 gates)
    const float so_ = r  * p2;
    const float r2  = r  * dd;
    const float tg  = fmaf(2.0f, r2 * p1, -1.0f); // tanh(g)
    const float r3  = r2 * dg;
    const float sf  = r3 * di;
    const float si  = r3 * df;
    c = fmaf(sf, c, si * tg);
    const float ec = ex2f(c * N2L2E);             // MUFU
    const float tc = fmaf(2.0f, rcpf(1.0f + ec), -1.0f);   // MUFU
    h = so_ * tc;
}

// pack two floats as f16x2 (round-to-nearest), a in low half
__device__ __forceinline__ unsigned pack_h2(float a, float b) {
    __half2 v = __halves2half2(__float2half_rn(a), __float2half_rn(b));
    return *(unsigned*)&v;
}
// split h into (hi, lo) f16 pair packed in one u32: low16 = hi part
__device__ __forceinline__ unsigned split_pack(float h) {
    const __half hi = __float2half_rn(h);
    const float  hf = __half2float(hi);
    const __half lo = __float2half_rn(h - hf);
    __half2 v = __halves2half2(hi, lo);
    return *(unsigned*)&v;
}
__device__ __forceinline__ float f16_residual(float w) {
    return w - __half2float(__float2half_rn(w));
}

__device__ __forceinline__ void mma16816(float d[4], const unsigned a[4], const unsigned b[2]) {
    asm volatile("mma.sync.aligned.m16n8k16.row.col.f32.f16.f16.f32 "
                 "{%0,%1,%2,%3}, {%4,%5,%6,%7}, {%8,%9}, {%0,%1,%2,%3};"
                 : "+f"(d[0]), "+f"(d[1]), "+f"(d[2]), "+f"(d[3])
                 : "r"(a[0]), "r"(a[1]), "r"(a[2]), "r"(a[3]),
                   "r"(b[0]), "r"(b[1]));
}

__device__ __forceinline__ float gelu_exact(float v) {
    return 0.5f * v * (1.0f + erff(v * 0.70710678118654752f));
}

// ---------------------------------------------------------------------------
// Kernel 1: fused depthwise-conv(5,pad2)+BN+GELU x2. One block per (b,c) row.
// ---------------------------------------------------------------------------
__global__ void __launch_bounds__(256) prep_kernel(
    const float* __restrict__ x,
    const float* __restrict__ c1w, const float* __restrict__ c1b,
    const float* __restrict__ b1g, const float* __restrict__ b1b,
    const float* __restrict__ b1m, const float* __restrict__ b1v,
    const float* __restrict__ c2w, const float* __restrict__ c2b,
    const float* __restrict__ b2g, const float* __restrict__ b2b,
    const float* __restrict__ b2m, const float* __restrict__ b2v)
{
    __shared__ float xs[TT + 4];
    __shared__ float ys[TT + 4];

    const int chain = blockIdx.x;
    const int ch    = chain & 63;
    const int tid   = threadIdx.x;

    if (tid < 2) {
        xs[tid] = 0.0f; xs[TT + 2 + tid] = 0.0f;
        ys[tid] = 0.0f; ys[TT + 2 + tid] = 0.0f;
    }
    const float* xr = x + (size_t)chain * TT;
    for (int t = tid; t < TT; t += 256) xs[t + 2] = xr[t];

    const float w0 = c1w[ch * 5 + 0], w1 = c1w[ch * 5 + 1], w2 = c1w[ch * 5 + 2],
                w3 = c1w[ch * 5 + 3], w4 = c1w[ch * 5 + 4];
    const float s1 = b1g[ch] * rsqrtf(b1v[ch] + 1e-5f);
    const float d1 = (c1b[ch] - b1m[ch]) * s1 + b1b[ch];

    __syncthreads();
    for (int t = tid; t < TT; t += 256) {
        float a = xs[t] * w0;
        a = fmaf(xs[t + 1], w1, a);
        a = fmaf(xs[t + 2], w2, a);
        a = fmaf(xs[t + 3], w3, a);
        a = fmaf(xs[t + 4], w4, a);
        ys[t + 2] = gelu_exact(fmaf(a, s1, d1));
    }

    const float u0 = c2w[ch * 5 + 0], u1 = c2w[ch * 5 + 1], u2 = c2w[ch * 5 + 2],
                u3 = c2w[ch * 5 + 3], u4 = c2w[ch * 5 + 4];
    const float s2 = b2g[ch] * rsqrtf(b2v[ch] + 1e-5f);
    const float d2 = (c2b[ch] - b2m[ch]) * s2 + b2b[ch];

    __syncthreads();
    float* outr = g_seq + (size_t)chain * TT;
    for (int t = tid; t < TT; t += 256) {
        float a = ys[t] * u0;
        a = fmaf(ys[t + 1], u1, a);
        a = fmaf(ys[t + 2], u2, a);
        a = fmaf(ys[t + 3], u3, a);
        a = fmaf(ys[t + 4], u4, a);
        outr[t] = gelu_exact(fmaf(a, s2, d2));
    }
}

// ---------------------------------------------------------------------------
// Kernel 2: LSTM via warp-level HMMA. One warp = 4 same-direction chains.
// Gates(64x8) = W(64x16) . H(16x8), 4 M-tiles (one per torch gate i,f,g,o),
// fp16 split inputs + fp32 accumulate => ~1e-7 gate error.
// Activations: 6 MUFU per unit-state (batched rcp + poly exp2 for tanh(g)).
// ---------------------------------------------------------------------------
__global__ void __launch_bounds__(128, 4) lstm_kernel(
    const float* __restrict__ wihf, const float* __restrict__ whhf,
    const float* __restrict__ bihf, const float* __restrict__ bhhf,
    const float* __restrict__ wihr, const float* __restrict__ whhr,
    const float* __restrict__ bihr, const float* __restrict__ bhhr)
{
    const int lane = threadIdx.x & 31;
    const int w    = blockIdx.x * 4 + (threadIdx.x >> 5);   // 0..2047
    const bool bwd = (w >= 1024);
    const int cb   = 4 * (bwd ? w - 1024 : w);              // chain base

    const float* wih = bwd ? wihr : wihf;
    const float* whh = bwd ? whhr : whhf;
    const float* bih = bwd ? bihr : bihf;
    const float* bhh = bwd ? bhhr : bhhf;

    const int g = lane >> 2;      // MMA group id
    const int t = lane & 3;       // MMA thread-in-group

    // ---- A fragments (W_hh split hi/lo), bias and w_ih per gate tile ----
    unsigned Ahi[4][4], Alo[4][4];
    float bb0[4], bb1[4], wi0[4], wi1[4];
#pragma unroll
    for (int m = 0; m < 4; m++) {
        const int r0 = m * 16 + g;
        const int r1 = r0 + 8;
        const float* W0 = whh + r0 * 16;
        const float* W1 = whh + r1 * 16;
        const float w00 = W0[2*t],   w01 = W0[2*t+1], w08 = W0[2*t+8], w09 = W0[2*t+9];
        const float w10 = W1[2*t],   w11 = W1[2*t+1], w18 = W1[2*t+8], w19 = W1[2*t+9];
        Ahi[m][0] = pack_h2(w00, w01);
        Ahi[m][1] = pack_h2(w10, w11);
        Ahi[m][2] = pack_h2(w08, w09);
        Ahi[m][3] = pack_h2(w18, w19);
        Alo[m][0] = pack_h2(f16_residual(w00), f16_residual(w01));
        Alo[m][1] = pack_h2(f16_residual(w10), f16_residual(w11));
        Alo[m][2] = pack_h2(f16_residual(w08), f16_residual(w09));
        Alo[m][3] = pack_h2(f16_residual(w18), f16_residual(w19));
        bb0[m] = bih[r0] + bhh[r0];
        bb1[m] = bih[r1] + bhh[r1];
        wi0[m] = wih[r0];
        wi1[m] = wih[r1];
    }

    // B-build source lanes: h(unit k, chain n) lives at lane 2k + (n>>1), slot n&1
    const int S0 = 4 * t + (g >> 1);        // k = 2t
    const int S1 = S0 + 2;                  // k = 2t+1
    const int S2 = S0 + 16;                 // k = 2t+8
    const int S3 = S0 + 18;                 // k = 2t+9
    const bool oddn = (g & 1);
    // Gate-redist source: quad (u = lane>>1, c pair = lane&1)
    const int SR = 4 * ((lane >> 1) & 7) + (lane & 1);
    const bool lowu = (lane < 16);          // u < 8

    // ---- state (ACT role): unit u = lane>>1, chains cb+2cp, cb+2cp+1 ----
    float c0 = 0.0f, h0 = 0.0f, c1 = 0.0f, h1 = 0.0f;
    unsigned hp0 = 0u, hp1 = 0u;            // split-packed h (f16 hi|lo)

    const int  s_lane = lane >> 2;          // staged step 0..7
    const int  c_lane = lane & 3;           // staged chain 0..3
    const float* seq_base = g_seq + (size_t)(cb + c_lane) * TT;

    for (int blk = 0; blk < 125; blk++) {
        const int tb = blk * 8;
        const int tg_ = tb + s_lane;
        const int xidx = bwd ? (TT - 1 - tg_) : tg_;
        const float xs = seq_base[xidx];    // x[chain c_lane][step s_lane]

#pragma unroll
        for (int s = 0; s < 8; s++) {
            // broadcast x for this step (real only for t<2)
            const float xA = __shfl_sync(0xffffffffu, xs, (2*t   + 4*s) & 31);
            const float xB = __shfl_sync(0xffffffffu, xs, (2*t+1 + 4*s) & 31);

            // D init: bias + w_ih * x
            float d[4][4];
#pragma unroll
            for (int m = 0; m < 4; m++) {
                d[m][0] = fmaf(wi0[m], xA, bb0[m]);
                d[m][1] = fmaf(wi0[m], xB, bb0[m]);
                d[m][2] = fmaf(wi1[m], xA, bb1[m]);
                d[m][3] = fmaf(wi1[m], xB, bb1[m]);
            }

            // build B fragments from previous h (split-packed)
            const unsigned q0a = __shfl_sync(0xffffffffu, hp0, S0);
            const unsigned q0b = __shfl_sync(0xffffffffu, hp1, S0);
            const unsigned q1a = __shfl_sync(0xffffffffu, hp0, S1);
            const unsigned q1b = __shfl_sync(0xffffffffu, hp1, S1);
            const unsigned q2a = __shfl_sync(0xffffffffu, hp0, S2);
            const unsigned q2b = __shfl_sync(0xffffffffu, hp1, S2);
            const unsigned q3a = __shfl_sync(0xffffffffu, hp0, S3);
            const unsigned q3b = __shfl_sync(0xffffffffu, hp1, S3);
            const unsigned p0 = oddn ? q0b : q0a;
            const unsigned p1 = oddn ? q1b : q1a;
            const unsigned p2 = oddn ? q2b : q2a;
            const unsigned p3 = oddn ? q3b : q3a;
            unsigned Bhi[2], Blo[2];
            Bhi[0] = __byte_perm(p0, p1, 0x5410);   // hi halves
            Bhi[1] = __byte_perm(p2, p3, 0x5410);
            Blo[0] = __byte_perm(p0, p1, 0x7632);   // lo halves
            Blo[1] = __byte_perm(p2, p3, 0x7632);

            // 12 HMMA: W_hi*h_hi + W_hi*h_lo + W_lo*h_hi (fp32 accumulate)
#pragma unroll
            for (int m = 0; m < 4; m++) {
                mma16816(d[m], Ahi[m], Bhi);
                mma16816(d[m], Ahi[m], Blo);
                mma16816(d[m], Alo[m], Bhi);
            }

            // redistribute gates: each lane collects its 2 quads
            float gA[4], gB[4];
#pragma unroll
            for (int m = 0; m < 4; m++) {
                const float va = __shfl_sync(0xffffffffu, d[m][0], SR);
                const float vb = __shfl_sync(0xffffffffu, d[m][1], SR);
                const float vc = __shfl_sync(0xffffffffu, d[m][2], SR);
                const float vd = __shfl_sync(0xffffffffu, d[m][3], SR);
                gA[m] = lowu ? va : vc;
                gB[m] = lowu ? vb : vd;
            }

            lstm_act(gA[0], gA[1], gA[2], gA[3], c0, h0);
            lstm_act(gB[0], gB[1], gB[2], gB[3], c1, h1);

            hp0 = split_pack(h0);
            hp1 = split_pack(h1);
        }
    }

    // write final h: lane owns (unit u = lane>>1, chains cb+2cp, cb+2cp+1)
    const int u  = lane >> 1;
    const int cp = lane & 1;
    const int off = bwd ? 16 : 0;
    g_feat[(cb + 2*cp)     * 32 + off + u] = h0;
    g_feat[(cb + 2*cp + 1) * 32 + off + u] = h1;
}

// ---------------------------------------------------------------------------
// Kernel 3: out[n,e] = feat[n,:] . lin_w[e,:] + lin_b[e]
// ---------------------------------------------------------------------------
__global__ void __launch_bounds__(256) linear_kernel(
    const float* __restrict__ lw, const float* __restrict__ lb,
    float* __restrict__ out)
{
    const int idx = blockIdx.x * 256 + threadIdx.x;    // 131072 total
    const int n = idx >> 5;
    const int e = idx & 31;
    const float* f = g_feat + n * 32;
    const float* wp = lw + e * 32;
    float acc = lb[e];
#pragma unroll
    for (int k = 0; k < 32; k++) acc = fmaf(f[k], wp[k], acc);
    out[idx] = acc;
}

// ---------------------------------------------------------------------------
extern "C" void kernel_launch(void* const* d_in, const int* in_sizes, int n_in,
                              void* d_out, int out_size)
{
    const float* x      = (const float*)d_in[0];
    const float* c1w    = (const float*)d_in[1];
    const float* c1b    = (const float*)d_in[2];
    const float* b1g    = (const float*)d_in[3];
    const float* b1b    = (const float*)d_in[4];
    const float* b1m    = (const float*)d_in[5];
    const float* b1v    = (const float*)d_in[6];
    const float* c2w    = (const float*)d_in[7];
    const float* c2b    = (const float*)d_in[8];
    const float* b2g    = (const float*)d_in[9];
    const float* b2b    = (const float*)d_in[10];
    const float* b2m    = (const float*)d_in[11];
    const float* b2v    = (const float*)d_in[12];
    const float* wihf   = (const float*)d_in[13];
    const float* whhf   = (const float*)d_in[14];
    const float* bihf   = (const float*)d_in[15];
    const float* bhhf   = (const float*)d_in[16];
    const float* wihr   = (const float*)d_in[17];
    const float* whhr   = (const float*)d_in[18];
    const float* bihr   = (const float*)d_in[19];
    const float* bhhr   = (const float*)d_in[20];
    const float* lw     = (const float*)d_in[21];
    const float* lb     = (const float*)d_in[22];
    float* out = (float*)d_out;

    prep_kernel<<<NCH, 256>>>(x, c1w, c1b, b1g, b1b, b1m, b1v,
                              c2w, c2b, b2g, b2b, b2m, b2v);
    lstm_kernel<<<512, 128>>>(wihf, whhf, bihf, bhhf,
                              wihr, whhr, bihr, bhhr);
    linear_kernel<<<(NCH * 32) / 256, 256>>>(lw, lb, out);
}

// round 7
// speedup vs baseline: 1.0494x; 1.0494x over previous
#include <cuda_runtime.h>
#include <cuda_fp16.h>

#define TT   1000
#define NCH  4096

// scratch (no cudaMalloc allowed)
__device__ float g_seq[NCH * TT];     // LSTM input, [chain][t], 16 MB
__device__ float g_feat[NCH * 32];    // [chain][ h_fwd(16) | h_bwd(16) ]

__device__ __forceinline__ float ex2f(float x) {
    float r; asm("ex2.approx.f32 %0, %1;" : "=f"(r) : "f"(x)); return r;
}
__device__ __forceinline__ float rcpf(float x) {
    float r; asm("rcp.approx.f32 %0, %1;" : "=f"(r) : "f"(x)); return r;
}

// FMA-pipe exp2: rint magic reduction + degree-6 Taylor. |x|<=60 clamped.
__device__ __forceinline__ float exp2_poly(float x) {
    x = fminf(fmaxf(x, -60.0f), 60.0f);
    const float MAGIC = 12582912.0f;              // 1.5 * 2^23
    const float tbig  = x + MAGIC;
    const float fi    = tbig - MAGIC;             // rint(x)
    const float f     = x - fi;
    const int   ii    = __float_as_int(tbig) - __float_as_int(MAGIC);
    const float sc    = __int_as_float((ii + 127) << 23);
    const float u     = f * 0.6931471805599453f;
    float p = fmaf(u, 1.3888889e-3f, 8.3333333e-3f);
    p = fmaf(p, u, 4.1666667e-2f);
    p = fmaf(p, u, 1.6666667e-1f);
    p = fmaf(p, u, 0.5f);
    p = fmaf(p, u, 1.0f);
    p = fmaf(p, u, 1.0f);
    return p * sc;
}

// 6-MUFU LSTM cell update (batched rcp for the 4 gates, poly exp2 for tanh(g))
__device__ __forceinline__ void lstm_act(float gi, float gf, float gg, float go,
                                         float& c, float& h) {
    const float NL2E  = -1.4426950408889634f;
    const float N2L2E = -2.8853900817779268f;
    const float ei = ex2f(gi * NL2E);             // MUFU
    const float ef = ex2f(gf * NL2E);             // MUFU
    const float eo = ex2f(go * NL2E);             // MUFU
    const float eg = exp2_poly(gg * N2L2E);       // FMA pipe
    const float di = 1.0f + ei, df = 1.0f + ef, dg = 1.0f + eg, dd = 1.0f + eo;
    const float p1 = di * df;
    const float p2 = p1 * dg;
    const float p3 = p2 * dd;
    const float r  = rcpf(p3);                    // MUFU
    const float so_ = r  * p2;
    const float r2  = r  * dd;
    const float tg  = fmaf(2.0f, r2 * p1, -1.0f);
    const float r3  = r2 * dg;
    const float sf  = r3 * di;
    const float si  = r3 * df;
    c = fmaf(sf, c, si * tg);
    const float ec = ex2f(c * N2L2E);             // MUFU
    const float tc = fmaf(2.0f, rcpf(1.0f + ec), -1.0f);   // MUFU
    h = so_ * tc;
}

__device__ __forceinline__ unsigned pack_h2(float a, float b) {
    __half2 v = __halves2half2(__float2half_rn(a), __float2half_rn(b));
    return *(unsigned*)&v;
}
__device__ __forceinline__ unsigned split_pack(float h) {
    const __half hi = __float2half_rn(h);
    const float  hf = __half2float(hi);
    const __half lo = __float2half_rn(h - hf);
    __half2 v = __halves2half2(hi, lo);
    return *(unsigned*)&v;
}
__device__ __forceinline__ float f16_residual(float w) {
    return w - __half2float(__float2half_rn(w));
}

__device__ __forceinline__ void mma16816(float d[4], const unsigned a[4], const unsigned b[2]) {
    asm volatile("mma.sync.aligned.m16n8k16.row.col.f32.f16.f16.f32 "
                 "{%0,%1,%2,%3}, {%4,%5,%6,%7}, {%8,%9}, {%0,%1,%2,%3};"
                 : "+f"(d[0]), "+f"(d[1]), "+f"(d[2]), "+f"(d[3])
                 : "r"(a[0]), "r"(a[1]), "r"(a[2]), "r"(a[3]),
                   "r"(b[0]), "r"(b[1]));
}

__device__ __forceinline__ float gelu_exact(float v) {
    return 0.5f * v * (1.0f + erff(v * 0.70710678118654752f));
}

// ---------------------------------------------------------------------------
// Kernel 1: fused depthwise-conv(5,pad2)+BN+GELU x2. One block per (b,c) row.
// ---------------------------------------------------------------------------
__global__ void __launch_bounds__(256) prep_kernel(
    const float* __restrict__ x,
    const float* __restrict__ c1w, const float* __restrict__ c1b,
    const float* __restrict__ b1g, const float* __restrict__ b1b,
    const float* __restrict__ b1m, const float* __restrict__ b1v,
    const float* __restrict__ c2w, const float* __restrict__ c2b,
    const float* __restrict__ b2g, const float* __restrict__ b2b,
    const float* __restrict__ b2m, const float* __restrict__ b2v)
{
    __shared__ float xs[TT + 4];
    __shared__ float ys[TT + 4];

    const int chain = blockIdx.x;
    const int ch    = chain & 63;
    const int tid   = threadIdx.x;

    if (tid < 2) {
        xs[tid] = 0.0f; xs[TT + 2 + tid] = 0.0f;
        ys[tid] = 0.0f; ys[TT + 2 + tid] = 0.0f;
    }
    const float* xr = x + (size_t)chain * TT;
    for (int t = tid; t < TT; t += 256) xs[t + 2] = xr[t];

    const float w0 = c1w[ch * 5 + 0], w1 = c1w[ch * 5 + 1], w2 = c1w[ch * 5 + 2],
                w3 = c1w[ch * 5 + 3], w4 = c1w[ch * 5 + 4];
    const float s1 = b1g[ch] * rsqrtf(b1v[ch] + 1e-5f);
    const float d1 = (c1b[ch] - b1m[ch]) * s1 + b1b[ch];

    __syncthreads();
    for (int t = tid; t < TT; t += 256) {
        float a = xs[t] * w0;
        a = fmaf(xs[t + 1], w1, a);
        a = fmaf(xs[t + 2], w2, a);
        a = fmaf(xs[t + 3], w3, a);
        a = fmaf(xs[t + 4], w4, a);
        ys[t + 2] = gelu_exact(fmaf(a, s1, d1));
    }

    const float u0 = c2w[ch * 5 + 0], u1 = c2w[ch * 5 + 1], u2 = c2w[ch * 5 + 2],
                u3 = c2w[ch * 5 + 3], u4 = c2w[ch * 5 + 4];
    const float s2 = b2g[ch] * rsqrtf(b2v[ch] + 1e-5f);
    const float d2 = (c2b[ch] - b2m[ch]) * s2 + b2b[ch];

    __syncthreads();
    float* outr = g_seq + (size_t)chain * TT;
    for (int t = tid; t < TT; t += 256) {
        float a = ys[t] * u0;
        a = fmaf(ys[t + 1], u1, a);
        a = fmaf(ys[t + 2], u2, a);
        a = fmaf(ys[t + 3], u3, a);
        a = fmaf(ys[t + 4], u4, a);
        outr[t] = gelu_exact(fmaf(a, s2, d2));
    }
}

// ---------------------------------------------------------------------------
// Kernel 2: LSTM via HMMA, 8 same-direction chains per warp (full N=8).
// Gates(64x8) = W(64x16) . H(16x8), 4 M-tiles (torch gates i,f,g,o),
// fp16 split-accumulate (3 MMAs per tile). h and gate exchange via per-warp
// smem (syncwarp only; warp is self-contained).
//
// MMA role: lane = 4g+t (g=0..7, t=0..3). Cols n = chains 0..7.
// ACT role: lane owns unit u = lane>>1 for chains 4cp..4cp+3 (cp = lane&1).
// ---------------------------------------------------------------------------
__global__ void __launch_bounds__(128) lstm_kernel(
    const float* __restrict__ wihf, const float* __restrict__ whhf,
    const float* __restrict__ bihf, const float* __restrict__ bhhf,
    const float* __restrict__ wihr, const float* __restrict__ whhr,
    const float* __restrict__ bihr, const float* __restrict__ bhhr)
{
    // per-warp buffers: h split-packed [2][16 units][8 chains + pad->20]
    __shared__ unsigned hsp_s[4][2][16][20];
    // gate exchange [4 tiles][16 units][8 chains]
    __shared__ float dbuf_s[4][4][16][8];

    const int tid  = threadIdx.x;
    const int wid  = tid >> 5;
    const int lane = tid & 31;
    const int wg   = blockIdx.x * 4 + wid;          // 0..1023
    const bool bwd = (wg >= 512);
    const int cb   = 8 * (bwd ? wg - 512 : wg);     // chain base (8 chains)

    const float* wih = bwd ? wihr : wihf;
    const float* whh = bwd ? whhr : whhf;
    const float* bih = bwd ? bihr : bihf;
    const float* bhh = bwd ? bhhr : bhhf;

    unsigned* hspW = &hsp_s[wid][0][0][0];
    float*    dbW  = &dbuf_s[wid][0][0][0];

    for (int i = lane; i < 2 * 16 * 20; i += 32) hspW[i] = 0u;
    __syncwarp();

    const int g = lane >> 2;      // MMA group / D row / B col(chain)
    const int t = lane & 3;       // MMA thread-in-group
    const int u = lane >> 1;      // ACT unit
    const int cp = lane & 1;      // ACT chain-quad selector

    // ---- A fragments (W_hh split hi/lo), bias and w_ih per gate tile ----
    unsigned Ahi[4][4], Alo[4][4];
    float bb0[4], bb1[4], wi0[4], wi1[4];
#pragma unroll
    for (int m = 0; m < 4; m++) {
        const int r0 = m * 16 + g;
        const int r1 = r0 + 8;
        const float* W0 = whh + r0 * 16;
        const float* W1 = whh + r1 * 16;
        const float w00 = W0[2*t],   w01 = W0[2*t+1], w08 = W0[2*t+8], w09 = W0[2*t+9];
        const float w10 = W1[2*t],   w11 = W1[2*t+1], w18 = W1[2*t+8], w19 = W1[2*t+9];
        Ahi[m][0] = pack_h2(w00, w01);
        Ahi[m][1] = pack_h2(w10, w11);
        Ahi[m][2] = pack_h2(w08, w09);
        Ahi[m][3] = pack_h2(w18, w19);
        Alo[m][0] = pack_h2(f16_residual(w00), f16_residual(w01));
        Alo[m][1] = pack_h2(f16_residual(w10), f16_residual(w11));
        Alo[m][2] = pack_h2(f16_residual(w08), f16_residual(w09));
        Alo[m][3] = pack_h2(f16_residual(w18), f16_residual(w19));
        bb0[m] = bih[r0] + bhh[r0];
        bb1[m] = bih[r1] + bhh[r1];
        wi0[m] = wih[r0];
        wi1[m] = wih[r1];
    }

    // x staging: lane = 4*chain + substep; coalesced 16B runs per chain
    const int xc  = lane >> 2;          // chain 0..7
    const int xs_ = lane & 3;           // substep 0..3
    const float* seqc = g_seq + (size_t)(cb + xc) * TT;

    float    c4[4]   = {0.0f, 0.0f, 0.0f, 0.0f};
    float    hout[4] = {0.0f, 0.0f, 0.0f, 0.0f};

    int par = 0;
    for (int r = 0; r < 250; r++) {
        const int tt = r * 4 + xs_;
        const float xv = seqc[bwd ? (TT - 1 - tt) : tt];

#pragma unroll
        for (int s = 0; s < 4; s++) {
            // broadcast x of chains 2t, 2t+1 for this step
            const float xA = __shfl_sync(0xffffffffu, xv, 8 * t + s);
            const float xB = __shfl_sync(0xffffffffu, xv, 8 * t + 4 + s);

            // D init: bias + w_ih * x  (rows g, g+8; cols 2t, 2t+1)
            float d[4][4];
#pragma unroll
            for (int m = 0; m < 4; m++) {
                d[m][0] = fmaf(wi0[m], xA, bb0[m]);
                d[m][1] = fmaf(wi0[m], xB, bb0[m]);
                d[m][2] = fmaf(wi1[m], xA, bb1[m]);
                d[m][3] = fmaf(wi1[m], xB, bb1[m]);
            }

            // B fragment: h(t-1) for k = 2t,2t+1,2t+8,2t+9 ; chain n = g
            const unsigned* hb = hspW + par * 320;
            const unsigned p0 = hb[(2 * t)     * 20 + g];
            const unsigned p1 = hb[(2 * t + 1) * 20 + g];
            const unsigned p2 = hb[(2 * t + 8) * 20 + g];
            const unsigned p3 = hb[(2 * t + 9) * 20 + g];
            unsigned Bhi[2], Blo[2];
            Bhi[0] = __byte_perm(p0, p1, 0x5410);
            Bhi[1] = __byte_perm(p2, p3, 0x5410);
            Blo[0] = __byte_perm(p0, p1, 0x7632);
            Blo[1] = __byte_perm(p2, p3, 0x7632);

            // 12 HMMA: W_hi*h_hi + W_hi*h_lo + W_lo*h_hi (fp32 accumulate)
#pragma unroll
            for (int m = 0; m < 4; m++) {
                mma16816(d[m], Ahi[m], Bhi);
                mma16816(d[m], Ahi[m], Blo);
                mma16816(d[m], Alo[m], Bhi);
            }

            // exchange gates via smem: [tile][unit][chain]
            float2* db2 = (float2*)dbW;
#pragma unroll
            for (int m = 0; m < 4; m++) {
                db2[m * 64 + g * 4 + t]       = make_float2(d[m][0], d[m][1]);
                db2[m * 64 + (g + 8) * 4 + t] = make_float2(d[m][2], d[m][3]);
            }
            __syncwarp();

            const float4* db4 = (const float4*)dbW;
            const float4 Gi = db4[0 * 32 + u * 2 + cp];
            const float4 Gf = db4[1 * 32 + u * 2 + cp];
            const float4 Gg = db4[2 * 32 + u * 2 + cp];
            const float4 Go = db4[3 * 32 + u * 2 + cp];

            lstm_act(Gi.x, Gf.x, Gg.x, Go.x, c4[0], hout[0]);
            lstm_act(Gi.y, Gf.y, Gg.y, Go.y, c4[1], hout[1]);
            lstm_act(Gi.z, Gf.z, Gg.z, Go.z, c4[2], hout[2]);
            lstm_act(Gi.w, Gf.w, Gg.w, Go.w, c4[3], hout[3]);

            const uint4 hq = make_uint4(split_pack(hout[0]), split_pack(hout[1]),
                                        split_pack(hout[2]), split_pack(hout[3]));
            *(uint4*)(hspW + (par ^ 1) * 320 + u * 20 + 4 * cp) = hq;
            __syncwarp();
            par ^= 1;
        }
    }

    const int off = bwd ? 16 : 0;
#pragma unroll
    for (int q = 0; q < 4; q++)
        g_feat[(cb + 4 * cp + q) * 32 + off + u] = hout[q];
}

// ---------------------------------------------------------------------------
// Kernel 3: out[n,e] = feat[n,:] . lin_w[e,:] + lin_b[e]
// ---------------------------------------------------------------------------
__global__ void __launch_bounds__(256) linear_kernel(
    const float* __restrict__ lw, const float* __restrict__ lb,
    float* __restrict__ out)
{
    const int idx = blockIdx.x * 256 + threadIdx.x;    // 131072 total
    const int n = idx >> 5;
    const int e = idx & 31;
    const float* f = g_feat + n * 32;
    const float* wp = lw + e * 32;
    float acc = lb[e];
#pragma unroll
    for (int k = 0; k < 32; k++) acc = fmaf(f[k], wp[k], acc);
    out[idx] = acc;
}

// ---------------------------------------------------------------------------
extern "C" void kernel_launch(void* const* d_in, const int* in_sizes, int n_in,
                              void* d_out, int out_size)
{
    const float* x      = (const float*)d_in[0];
    const float* c1w    = (const float*)d_in[1];
    const float* c1b    = (const float*)d_in[2];
    const float* b1g    = (const float*)d_in[3];
    const float* b1b    = (const float*)d_in[4];
    const float* b1m    = (const float*)d_in[5];
    const float* b1v    = (const float*)d_in[6];
    const float* c2w    = (const float*)d_in[7];
    const float* c2b    = (const float*)d_in[8];
    const float* b2g    = (const float*)d_in[9];
    const float* b2b    = (const float*)d_in[10];
    const float* b2m    = (const float*)d_in[11];
    const float* b2v    = (const float*)d_in[12];
    const float* wihf   = (const float*)d_in[13];
    const float* whhf   = (const float*)d_in[14];
    const float* bihf   = (const float*)d_in[15];
    const float* bhhf   = (const float*)d_in[16];
    const float* wihr   = (const float*)d_in[17];
    const float* whhr   = (const float*)d_in[18];
    const float* bihr   = (const float*)d_in[19];
    const float* bhhr   = (const float*)d_in[20];
    const float* lw     = (const float*)d_in[21];
    const float* lb     = (const float*)d_in[22];
    float* out = (float*)d_out;

    prep_kernel<<<NCH, 256>>>(x, c1w, c1b, b1g, b1b, b1m, b1v,
                              c2w, c2b, b2g, b2b, b2m, b2v);
    lstm_kernel<<<256, 128>>>(wihf, whhf, bihf, bhhf,
                              wihr, whhr, bihr, bhhr);
    linear_kernel<<<(NCH * 32) / 256, 256>>>(lw, lb, out);
}

// round 8
// speedup vs baseline: 1.1911x; 1.1351x over previous
#include <cuda_runtime.h>
#include <cuda_fp16.h>

#define TT   1000
#define NCH  4096

// scratch (no cudaMalloc allowed)
__device__ float g_seq[NCH * TT];     // LSTM input, [chain][t], 16 MB
__device__ float g_feat[NCH * 32];    // [chain][ h_fwd(16) | h_bwd(16) ]

__device__ __forceinline__ float ex2f(float x) {
    float r; asm("ex2.approx.f32 %0, %1;" : "=f"(r) : "f"(x)); return r;
}
__device__ __forceinline__ float rcpf(float x) {
    float r; asm("rcp.approx.f32 %0, %1;" : "=f"(r) : "f"(x)); return r;
}

// 7-MUFU, ~19-FMA LSTM cell update.
// sigmoid(x) = 1/(1+2^(-x log2e)), tanh(x) = 2/(1+2^(-2x log2e)) - 1.
// The four gate denominators are inverted with ONE rcp (Montgomery batch).
// Products bounded (|gate| <~ 10 by weight-scale) => no overflow; validated R6.
__device__ __forceinline__ void lstm_act(float gi, float gf, float gg, float go,
                                         float& c, float& h) {
    const float NL2E  = -1.4426950408889634f;
    const float N2L2E = -2.8853900817779268f;
    const float ei = ex2f(gi * NL2E);             // MUFU
    const float ef = ex2f(gf * NL2E);             // MUFU
    const float eo = ex2f(go * NL2E);             // MUFU
    const float eg = ex2f(gg * N2L2E);            // MUFU
    const float di = 1.0f + ei, df = 1.0f + ef, dg = 1.0f + eg, dd = 1.0f + eo;
    const float p1 = di * df;
    const float p2 = p1 * dg;
    const float p3 = p2 * dd;
    const float r  = rcpf(p3);                    // MUFU (1 rcp for 4 gates)
    const float so_ = r  * p2;                    // sigmoid(go)
    const float r2  = r  * dd;
    const float tg  = fmaf(2.0f, r2 * p1, -1.0f); // tanh(gg)
    const float r3  = r2 * dg;
    const float sf  = r3 * di;                    // sigmoid(gf)
    const float si  = r3 * df;                    // sigmoid(gi)
    c = fmaf(sf, c, si * tg);
    const float ec = ex2f(c * N2L2E);             // MUFU
    const float tc = fmaf(2.0f, rcpf(1.0f + ec), -1.0f);   // MUFU
    h = so_ * tc;
}

__device__ __forceinline__ unsigned pack_h2(float a, float b) {
    __half2 v = __halves2half2(__float2half_rn(a), __float2half_rn(b));
    return *(unsigned*)&v;
}
__device__ __forceinline__ unsigned split_pack(float h) {
    const __half hi = __float2half_rn(h);
    const float  hf = __half2float(hi);
    const __half lo = __float2half_rn(h - hf);
    __half2 v = __halves2half2(hi, lo);
    return *(unsigned*)&v;
}
__device__ __forceinline__ float f16_residual(float w) {
    return w - __half2float(__float2half_rn(w));
}

__device__ __forceinline__ void mma16816(float d[4], const unsigned a[4], const unsigned b[2]) {
    asm volatile("mma.sync.aligned.m16n8k16.row.col.f32.f16.f16.f32 "
                 "{%0,%1,%2,%3}, {%4,%5,%6,%7}, {%8,%9}, {%0,%1,%2,%3};"
                 : "+f"(d[0]), "+f"(d[1]), "+f"(d[2]), "+f"(d[3])
                 : "r"(a[0]), "r"(a[1]), "r"(a[2]), "r"(a[3]),
                   "r"(b[0]), "r"(b[1]));
}

__device__ __forceinline__ float gelu_exact(float v) {
    return 0.5f * v * (1.0f + erff(v * 0.70710678118654752f));
}

// ---------------------------------------------------------------------------
// Kernel 1: fused depthwise-conv(5,pad2)+BN+GELU x2. One block per (b,c) row.
// ---------------------------------------------------------------------------
__global__ void __launch_bounds__(256) prep_kernel(
    const float* __restrict__ x,
    const float* __restrict__ c1w, const float* __restrict__ c1b,
    const float* __restrict__ b1g, const float* __restrict__ b1b,
    const float* __restrict__ b1m, const float* __restrict__ b1v,
    const float* __restrict__ c2w, const float* __restrict__ c2b,
    const float* __restrict__ b2g, const float* __restrict__ b2b,
    const float* __restrict__ b2m, const float* __restrict__ b2v)
{
    __shared__ float xs[TT + 4];
    __shared__ float ys[TT + 4];

    const int chain = blockIdx.x;
    const int ch    = chain & 63;
    const int tid   = threadIdx.x;

    if (tid < 2) {
        xs[tid] = 0.0f; xs[TT + 2 + tid] = 0.0f;
        ys[tid] = 0.0f; ys[TT + 2 + tid] = 0.0f;
    }
    const float* xr = x + (size_t)chain * TT;
    for (int t = tid; t < TT; t += 256) xs[t + 2] = xr[t];

    const float w0 = c1w[ch * 5 + 0], w1 = c1w[ch * 5 + 1], w2 = c1w[ch * 5 + 2],
                w3 = c1w[ch * 5 + 3], w4 = c1w[ch * 5 + 4];
    const float s1 = b1g[ch] * rsqrtf(b1v[ch] + 1e-5f);
    const float d1 = (c1b[ch] - b1m[ch]) * s1 + b1b[ch];

    __syncthreads();
    for (int t = tid; t < TT; t += 256) {
        float a = xs[t] * w0;
        a = fmaf(xs[t + 1], w1, a);
        a = fmaf(xs[t + 2], w2, a);
        a = fmaf(xs[t + 3], w3, a);
        a = fmaf(xs[t + 4], w4, a);
        ys[t + 2] = gelu_exact(fmaf(a, s1, d1));
    }

    const float u0 = c2w[ch * 5 + 0], u1 = c2w[ch * 5 + 1], u2 = c2w[ch * 5 + 2],
                u3 = c2w[ch * 5 + 3], u4 = c2w[ch * 5 + 4];
    const float s2 = b2g[ch] * rsqrtf(b2v[ch] + 1e-5f);
    const float d2 = (c2b[ch] - b2m[ch]) * s2 + b2b[ch];

    __syncthreads();
    float* outr = g_seq + (size_t)chain * TT;
    for (int t = tid; t < TT; t += 256) {
        float a = ys[t] * u0;
        a = fmaf(ys[t + 1], u1, a);
        a = fmaf(ys[t + 2], u2, a);
        a = fmaf(ys[t + 3], u3, a);
        a = fmaf(ys[t + 4], u4, a);
        outr[t] = gelu_exact(fmaf(a, s2, d2));
    }
}

// ---------------------------------------------------------------------------
// Kernel 2: LSTM via HMMA, 8 same-direction chains per warp (full N=8).
// Gates(64x8) = W(64x16) . H(16x8), 4 M-tiles (torch gates i,f,g,o),
// fp16 split-accumulate (3 MMAs per tile). h and gate exchange via per-warp
// smem (syncwarp only; warp is self-contained).
// ---------------------------------------------------------------------------
__global__ void __launch_bounds__(128) lstm_kernel(
    const float* __restrict__ wihf, const float* __restrict__ whhf,
    const float* __restrict__ bihf, const float* __restrict__ bhhf,
    const float* __restrict__ wihr, const float* __restrict__ whhr,
    const float* __restrict__ bihr, const float* __restrict__ bhhr)
{
    // per-warp buffers: h split-packed [2][16 units][8 chains + pad->20]
    __shared__ unsigned hsp_s[4][2][16][20];
    // gate exchange [4 tiles][16 units][8 chains]
    __shared__ float dbuf_s[4][4][16][8];

    const int tid  = threadIdx.x;
    const int wid  = tid >> 5;
    const int lane = tid & 31;
    const int wg   = blockIdx.x * 4 + wid;          // 0..1023
    const bool bwd = (wg >= 512);
    const int cb   = 8 * (bwd ? wg - 512 : wg);     // chain base (8 chains)

    const float* wih = bwd ? wihr : wihf;
    const float* whh = bwd ? whhr : whhf;
    const float* bih = bwd ? bihr : bihf;
    const float* bhh = bwd ? bhhr : bhhf;

    unsigned* hspW = &hsp_s[wid][0][0][0];
    float*    dbW  = &dbuf_s[wid][0][0][0];

    for (int i = lane; i < 2 * 16 * 20; i += 32) hspW[i] = 0u;
    __syncwarp();

    const int g = lane >> 2;      // MMA group / D row / B col(chain)
    const int t = lane & 3;       // MMA thread-in-group
    const int u = lane >> 1;      // ACT unit
    const int cp = lane & 1;      // ACT chain-quad selector

    // ---- A fragments (W_hh split hi/lo), bias and w_ih per gate tile ----
    unsigned Ahi[4][4], Alo[4][4];
    float bb0[4], bb1[4], wi0[4], wi1[4];
#pragma unroll
    for (int m = 0; m < 4; m++) {
        const int r0 = m * 16 + g;
        const int r1 = r0 + 8;
        const float* W0 = whh + r0 * 16;
        const float* W1 = whh + r1 * 16;
        const float w00 = W0[2*t],   w01 = W0[2*t+1], w08 = W0[2*t+8], w09 = W0[2*t+9];
        const float w10 = W1[2*t],   w11 = W1[2*t+1], w18 = W1[2*t+8], w19 = W1[2*t+9];
        Ahi[m][0] = pack_h2(w00, w01);
        Ahi[m][1] = pack_h2(w10, w11);
        Ahi[m][2] = pack_h2(w08, w09);
        Ahi[m][3] = pack_h2(w18, w19);
        Alo[m][0] = pack_h2(f16_residual(w00), f16_residual(w01));
        Alo[m][1] = pack_h2(f16_residual(w10), f16_residual(w11));
        Alo[m][2] = pack_h2(f16_residual(w08), f16_residual(w09));
        Alo[m][3] = pack_h2(f16_residual(w18), f16_residual(w19));
        bb0[m] = bih[r0] + bhh[r0];
        bb1[m] = bih[r1] + bhh[r1];
        wi0[m] = wih[r0];
        wi1[m] = wih[r1];
    }

    // x staging: lane = 4*chain + substep; coalesced 16B runs per chain
    const int xc  = lane >> 2;          // chain 0..7
    const int xs_ = lane & 3;           // substep 0..3
    const float* seqc = g_seq + (size_t)(cb + xc) * TT;

    float    c4[4]   = {0.0f, 0.0f, 0.0f, 0.0f};
    float    hout[4] = {0.0f, 0.0f, 0.0f, 0.0f};

    int par = 0;
    for (int r = 0; r < 250; r++) {
        const int tt = r * 4 + xs_;
        const float xv = seqc[bwd ? (TT - 1 - tt) : tt];

#pragma unroll
        for (int s = 0; s < 4; s++) {
            // broadcast x of chains 2t, 2t+1 for this step
            const float xA = __shfl_sync(0xffffffffu, xv, 8 * t + s);
            const float xB = __shfl_sync(0xffffffffu, xv, 8 * t + 4 + s);

            // D init: bias + w_ih * x  (rows g, g+8; cols 2t, 2t+1)
            float d[4][4];
#pragma unroll
            for (int m = 0; m < 4; m++) {
                d[m][0] = fmaf(wi0[m], xA, bb0[m]);
                d[m][1] = fmaf(wi0[m], xB, bb0[m]);
                d[m][2] = fmaf(wi1[m], xA, bb1[m]);
                d[m][3] = fmaf(wi1[m], xB, bb1[m]);
            }

            // B fragment: h(t-1) for k = 2t,2t+1,2t+8,2t+9 ; chain n = g
            const unsigned* hb = hspW + par * 320;
            const unsigned p0 = hb[(2 * t)     * 20 + g];
            const unsigned p1 = hb[(2 * t + 1) * 20 + g];
            const unsigned p2 = hb[(2 * t + 8) * 20 + g];
            const unsigned p3 = hb[(2 * t + 9) * 20 + g];
            unsigned Bhi[2], Blo[2];
            Bhi[0] = __byte_perm(p0, p1, 0x5410);
            Bhi[1] = __byte_perm(p2, p3, 0x5410);
            Blo[0] = __byte_perm(p0, p1, 0x7632);
            Blo[1] = __byte_perm(p2, p3, 0x7632);

            // 12 HMMA: W_hi*h_hi + W_hi*h_lo + W_lo*h_hi (fp32 accumulate)
#pragma unroll
            for (int m = 0; m < 4; m++) {
                mma16816(d[m], Ahi[m], Bhi);
                mma16816(d[m], Ahi[m], Blo);
                mma16816(d[m], Alo[m], Bhi);
            }

            // exchange gates via smem: [tile][unit][chain]
            float2* db2 = (float2*)dbW;
#pragma unroll
            for (int m = 0; m < 4; m++) {
                db2[m * 64 + g * 4 + t]       = make_float2(d[m][0], d[m][1]);
                db2[m * 64 + (g + 8) * 4 + t] = make_float2(d[m][2], d[m][3]);
            }
            __syncwarp();

            const float4* db4 = (const float4*)dbW;
            const float4 Gi = db4[0 * 32 + u * 2 + cp];
            const float4 Gf = db4[1 * 32 + u * 2 + cp];
            const float4 Gg = db4[2 * 32 + u * 2 + cp];
            const float4 Go = db4[3 * 32 + u * 2 + cp];

            lstm_act(Gi.x, Gf.x, Gg.x, Go.x, c4[0], hout[0]);
            lstm_act(Gi.y, Gf.y, Gg.y, Go.y, c4[1], hout[1]);
            lstm_act(Gi.z, Gf.z, Gg.z, Go.z, c4[2], hout[2]);
            lstm_act(Gi.w, Gf.w, Gg.w, Go.w, c4[3], hout[3]);

            const uint4 hq = make_uint4(split_pack(hout[0]), split_pack(hout[1]),
                                        split_pack(hout[2]), split_pack(hout[3]));
            *(uint4*)(hspW + (par ^ 1) * 320 + u * 20 + 4 * cp) = hq;
            __syncwarp();
            par ^= 1;
        }
    }

    const int off = bwd ? 16 : 0;
#pragma unroll
    for (int q = 0; q < 4; q++)
        g_feat[(cb + 4 * cp + q) * 32 + off + u] = hout[q];
}

// ---------------------------------------------------------------------------
// Kernel 3: out[n,e] = feat[n,:] . lin_w[e,:] + lin_b[e]
// ---------------------------------------------------------------------------
__global__ void __launch_bounds__(256) linear_kernel(
    const float* __restrict__ lw, const float* __restrict__ lb,
    float* __restrict__ out)
{
    const int idx = blockIdx.x * 256 + threadIdx.x;    // 131072 total
    const int n = idx >> 5;
    const int e = idx & 31;
    const float* f = g_feat + n * 32;
    const float* wp = lw + e * 32;
    float acc = lb[e];
#pragma unroll
    for (int k = 0; k < 32; k++) acc = fmaf(f[k], wp[k], acc);
    out[idx] = acc;
}

// ---------------------------------------------------------------------------
extern "C" void kernel_launch(void* const* d_in, const int* in_sizes, int n_in,
                              void* d_out, int out_size)
{
    const float* x      = (const float*)d_in[0];
    const float* c1w    = (const float*)d_in[1];
    const float* c1b    = (const float*)d_in[2];
    const float* b1g    = (const float*)d_in[3];
    const float* b1b    = (const float*)d_in[4];
    const float* b1m    = (const float*)d_in[5];
    const float* b1v    = (const float*)d_in[6];
    const float* c2w    = (const float*)d_in[7];
    const float* c2b    = (const float*)d_in[8];
    const float* b2g    = (const float*)d_in[9];
    const float* b2b    = (const float*)d_in[10];
    const float* b2m    = (const float*)d_in[11];
    const float* b2v    = (const float*)d_in[12];
    const float* wihf   = (const float*)d_in[13];
    const float* whhf   = (const float*)d_in[14];
    const float* bihf   = (const float*)d_in[15];
    const float* bhhf   = (const float*)d_in[16];
    const float* wihr   = (const float*)d_in[17];
    const float* whhr   = (const float*)d_in[18];
    const float* bihr   = (const float*)d_in[19];
    const float* bhhr   = (const float*)d_in[20];
    const float* lw     = (const float*)d_in[21];
    const float* lb     = (const float*)d_in[22];
    float* out = (float*)d_out;

    prep_kernel<<<NCH, 256>>>(x, c1w, c1b, b1g, b1b, b1m, b1v,
                              c2w, c2b, b2g, b2b, b2m, b2v);
    lstm_kernel<<<256, 128>>>(wihf, whhf, bihf, bhhf,
                              wihr, whhr, bihr, bhhr);
    linear_kernel<<<(NCH * 32) / 256, 256>>>(lw, lb, out);
}

// round 9
// speedup vs baseline: 1.3630x; 1.1443x over previous
#include <cuda_runtime.h>
#include <cuda_fp16.h>

#define TT   1000
#define NCH  4096

// scratch (no cudaMalloc allowed)
__device__ float g_seq[NCH * TT];     // LSTM input, [chain][t], 16 MB
__device__ float g_feat[NCH * 32];    // [chain][ h_fwd(16) | h_bwd(16) ]

__device__ __forceinline__ float ex2f(float x) {
    float r; asm("ex2.approx.f32 %0, %1;" : "=f"(r) : "f"(x)); return r;
}
__device__ __forceinline__ float rcpf(float x) {
    float r; asm("rcp.approx.f32 %0, %1;" : "=f"(r) : "f"(x)); return r;
}

// 7-MUFU LSTM cell update (batched single-rcp for the 4 gate denominators).
__device__ __forceinline__ void lstm_act(float gi, float gf, float gg, float go,
                                         float& c, float& h) {
    const float NL2E  = -1.4426950408889634f;
    const float N2L2E = -2.8853900817779268f;
    const float ei = ex2f(gi * NL2E);             // MUFU
    const float ef = ex2f(gf * NL2E);             // MUFU
    const float eo = ex2f(go * NL2E);             // MUFU
    const float eg = ex2f(gg * N2L2E);            // MUFU
    const float di = 1.0f + ei, df = 1.0f + ef, dg = 1.0f + eg, dd = 1.0f + eo;
    const float p1 = di * df;
    const float p2 = p1 * dg;
    const float p3 = p2 * dd;
    const float r  = rcpf(p3);                    // MUFU (1 rcp for 4 gates)
    const float so_ = r  * p2;                    // sigmoid(go)
    const float r2  = r  * dd;
    const float tg  = fmaf(2.0f, r2 * p1, -1.0f); // tanh(gg)
    const float r3  = r2 * dg;
    const float sf  = r3 * di;                    // sigmoid(gf)
    const float si  = r3 * df;                    // sigmoid(gi)
    c = fmaf(sf, c, si * tg);
    const float ec = ex2f(c * N2L2E);             // MUFU
    const float tc = fmaf(2.0f, rcpf(1.0f + ec), -1.0f);   // MUFU
    h = so_ * tc;
}

__device__ __forceinline__ unsigned pack_h2(float a, float b) {
    __half2 v = __halves2half2(__float2half_rn(a), __float2half_rn(b));
    return *(unsigned*)&v;
}
__device__ __forceinline__ unsigned split_pack(float h) {
    const __half hi = __float2half_rn(h);
    const float  hf = __half2float(hi);
    const __half lo = __float2half_rn(h - hf);
    __half2 v = __halves2half2(hi, lo);
    return *(unsigned*)&v;
}
__device__ __forceinline__ float f16_residual(float w) {
    return w - __half2float(__float2half_rn(w));
}

__device__ __forceinline__ void mma16816(float d[4], const unsigned a[4], const unsigned b[2]) {
    asm volatile("mma.sync.aligned.m16n8k16.row.col.f32.f16.f16.f32 "
                 "{%0,%1,%2,%3}, {%4,%5,%6,%7}, {%8,%9}, {%0,%1,%2,%3};"
                 : "+f"(d[0]), "+f"(d[1]), "+f"(d[2]), "+f"(d[3])
                 : "r"(a[0]), "r"(a[1]), "r"(a[2]), "r"(a[3]),
                   "r"(b[0]), "r"(b[1]));
}

__device__ __forceinline__ float gelu_exact(float v) {
    return 0.5f * v * (1.0f + erff(v * 0.70710678118654752f));
}

// ---------------------------------------------------------------------------
// Kernel 1: fused depthwise-conv(5,pad2)+BN+GELU x2. One block per (b,c) row.
// ---------------------------------------------------------------------------
__global__ void __launch_bounds__(256) prep_kernel(
    const float* __restrict__ x,
    const float* __restrict__ c1w, const float* __restrict__ c1b,
    const float* __restrict__ b1g, const float* __restrict__ b1b,
    const float* __restrict__ b1m, const float* __restrict__ b1v,
    const float* __restrict__ c2w, const float* __restrict__ c2b,
    const float* __restrict__ b2g, const float* __restrict__ b2b,
    const float* __restrict__ b2m, const float* __restrict__ b2v)
{
    __shared__ float xs[TT + 4];
    __shared__ float ys[TT + 4];

    const int chain = blockIdx.x;
    const int ch    = chain & 63;
    const int tid   = threadIdx.x;

    if (tid < 2) {
        xs[tid] = 0.0f; xs[TT + 2 + tid] = 0.0f;
        ys[tid] = 0.0f; ys[TT + 2 + tid] = 0.0f;
    }
    const float* xr = x + (size_t)chain * TT;
    for (int t = tid; t < TT; t += 256) xs[t + 2] = xr[t];

    const float w0 = c1w[ch * 5 + 0], w1 = c1w[ch * 5 + 1], w2 = c1w[ch * 5 + 2],
                w3 = c1w[ch * 5 + 3], w4 = c1w[ch * 5 + 4];
    const float s1 = b1g[ch] * rsqrtf(b1v[ch] + 1e-5f);
    const float d1 = (c1b[ch] - b1m[ch]) * s1 + b1b[ch];

    __syncthreads();
    for (int t = tid; t < TT; t += 256) {
        float a = xs[t] * w0;
        a = fmaf(xs[t + 1], w1, a);
        a = fmaf(xs[t + 2], w2, a);
        a = fmaf(xs[t + 3], w3, a);
        a = fmaf(xs[t + 4], w4, a);
        ys[t + 2] = gelu_exact(fmaf(a, s1, d1));
    }

    const float u0 = c2w[ch * 5 + 0], u1 = c2w[ch * 5 + 1], u2 = c2w[ch * 5 + 2],
                u3 = c2w[ch * 5 + 3], u4 = c2w[ch * 5 + 4];
    const float s2 = b2g[ch] * rsqrtf(b2v[ch] + 1e-5f);
    const float d2 = (c2b[ch] - b2m[ch]) * s2 + b2b[ch];

    __syncthreads();
    float* outr = g_seq + (size_t)chain * TT;
    for (int t = tid; t < TT; t += 256) {
        float a = ys[t] * u0;
        a = fmaf(ys[t + 1], u1, a);
        a = fmaf(ys[t + 2], u2, a);
        a = fmaf(ys[t + 3], u3, a);
        a = fmaf(ys[t + 4], u4, a);
        outr[t] = gelu_exact(fmaf(a, s2, d2));
    }
}

// ---------------------------------------------------------------------------
// Kernel 2: LSTM via HMMA, 8 same-direction chains per warp (full N=8).
// Gates(64x8) = W(64x16) . H(16x8), 4 M-tiles (torch gates i,f,g,o),
// fp16 split-accumulate (3 MMAs per tile).
//
// KEY (R9): NO gate exchange. Lane (g,t)'s D fragments already hold ALL FOUR
// gates for states (unit g, chain 2t), (g, 2t+1), (g+8, 2t), (g+8, 2t+1):
// d[m][0..3], m = gate. Activate in place; publish only h to per-warp smem
// for the next step's B fragment. ONE syncwarp per step.
// ---------------------------------------------------------------------------
__global__ void __launch_bounds__(128) lstm_kernel(
    const float* __restrict__ wihf, const float* __restrict__ whhf,
    const float* __restrict__ bihf, const float* __restrict__ bhhf,
    const float* __restrict__ wihr, const float* __restrict__ whhr,
    const float* __restrict__ bihr, const float* __restrict__ bhhr)
{
    // per-warp h buffer, split-packed f16(hi|lo): [2 parity][16 units][8 ch + pad->20]
    __shared__ unsigned hsp_s[4][2][16][20];

    const int tid  = threadIdx.x;
    const int wid  = tid >> 5;
    const int lane = tid & 31;
    const int wg   = blockIdx.x * 4 + wid;          // 0..1023
    const bool bwd = (wg >= 512);
    const int cb   = 8 * (bwd ? wg - 512 : wg);     // chain base (8 chains)

    const float* wih = bwd ? wihr : wihf;
    const float* whh = bwd ? whhr : whhf;
    const float* bih = bwd ? bihr : bihf;
    const float* bhh = bwd ? bhhr : bhhf;

    unsigned* hspW = &hsp_s[wid][0][0][0];
    for (int i = lane; i < 2 * 16 * 20; i += 32) hspW[i] = 0u;

    const int g = lane >> 2;      // MMA group: D rows g, g+8; B col(chain) g
    const int t = lane & 3;       // MMA thread-in-group: D cols 2t, 2t+1

    // ---- A fragments (W_hh split hi/lo), bias and w_ih per gate tile ----
    unsigned Ahi[4][4], Alo[4][4];
    float bb0[4], bb1[4], wi0[4], wi1[4];
#pragma unroll
    for (int m = 0; m < 4; m++) {
        const int r0 = m * 16 + g;
        const int r1 = r0 + 8;
        const float* W0 = whh + r0 * 16;
        const float* W1 = whh + r1 * 16;
        const float w00 = W0[2*t],   w01 = W0[2*t+1], w08 = W0[2*t+8], w09 = W0[2*t+9];
        const float w10 = W1[2*t],   w11 = W1[2*t+1], w18 = W1[2*t+8], w19 = W1[2*t+9];
        Ahi[m][0] = pack_h2(w00, w01);
        Ahi[m][1] = pack_h2(w10, w11);
        Ahi[m][2] = pack_h2(w08, w09);
        Ahi[m][3] = pack_h2(w18, w19);
        Alo[m][0] = pack_h2(f16_residual(w00), f16_residual(w01));
        Alo[m][1] = pack_h2(f16_residual(w10), f16_residual(w11));
        Alo[m][2] = pack_h2(f16_residual(w08), f16_residual(w09));
        Alo[m][3] = pack_h2(f16_residual(w18), f16_residual(w19));
        bb0[m] = bih[r0] + bhh[r0];
        bb1[m] = bih[r1] + bhh[r1];
        wi0[m] = wih[r0];
        wi1[m] = wih[r1];
    }

    // x staging: lane = 4*chain + substep; coalesced 16B runs per chain
    const int xc  = lane >> 2;          // chain 0..7
    const int xs_ = lane & 3;           // substep 0..3
    const float* seqc = g_seq + (size_t)(cb + xc) * TT;

    // states owned by this lane: q=0 ->(g,2t)  q=1 ->(g,2t+1)
    //                            q=2 ->(g+8,2t) q=3 ->(g+8,2t+1)
    float c4[4]   = {0.0f, 0.0f, 0.0f, 0.0f};
    float hout[4] = {0.0f, 0.0f, 0.0f, 0.0f};

    int par = 0;
    for (int r = 0; r < 250; r++) {
        const int tt = r * 4 + xs_;
        const float xv = seqc[bwd ? (TT - 1 - tt) : tt];

#pragma unroll
        for (int s = 0; s < 4; s++) {
            __syncwarp();      // prev step's h writes -> visible for B-build

            // broadcast x of chains 2t, 2t+1 for this step
            const float xA = __shfl_sync(0xffffffffu, xv, 8 * t + s);
            const float xB = __shfl_sync(0xffffffffu, xv, 8 * t + 4 + s);

            // B fragment: h(t-1) for k = 2t,2t+1,2t+8,2t+9 ; chain n = g
            const unsigned* hb = hspW + par * 320;
            const unsigned p0 = hb[(2 * t)     * 20 + g];
            const unsigned p1 = hb[(2 * t + 1) * 20 + g];
            const unsigned p2 = hb[(2 * t + 8) * 20 + g];
            const unsigned p3 = hb[(2 * t + 9) * 20 + g];
            unsigned Bhi[2], Blo[2];
            Bhi[0] = __byte_perm(p0, p1, 0x5410);
            Bhi[1] = __byte_perm(p2, p3, 0x5410);
            Blo[0] = __byte_perm(p0, p1, 0x7632);
            Blo[1] = __byte_perm(p2, p3, 0x7632);

            // D init: bias + w_ih * x  (rows g, g+8; cols 2t, 2t+1)
            float d[4][4];
#pragma unroll
            for (int m = 0; m < 4; m++) {
                d[m][0] = fmaf(wi0[m], xA, bb0[m]);
                d[m][1] = fmaf(wi0[m], xB, bb0[m]);
                d[m][2] = fmaf(wi1[m], xA, bb1[m]);
                d[m][3] = fmaf(wi1[m], xB, bb1[m]);
            }

            // 12 HMMA: W_hi*h_hi + W_hi*h_lo + W_lo*h_hi (fp32 accumulate)
#pragma unroll
            for (int m = 0; m < 4; m++) {
                mma16816(d[m], Ahi[m], Bhi);
                mma16816(d[m], Ahi[m], Blo);
                mma16816(d[m], Alo[m], Bhi);
            }

            // activate IN PLACE: d[m][q] = gate m of this lane's state q
#pragma unroll
            for (int q = 0; q < 4; q++)
                lstm_act(d[0][q], d[1][q], d[2][q], d[3][q], c4[q], hout[q]);

            // publish h for next step's B-build (chains 2t,2t+1 contiguous)
            unsigned* ho = hspW + (par ^ 1) * 320;
            *(uint2*)(ho + g * 20 + 2 * t) =
                make_uint2(split_pack(hout[0]), split_pack(hout[1]));
            *(uint2*)(ho + (g + 8) * 20 + 2 * t) =
                make_uint2(split_pack(hout[2]), split_pack(hout[3]));

            par ^= 1;
        }
    }

    // final h: lane owns (unit g, chains cb+2t, cb+2t+1) and (unit g+8, same)
    const int off = bwd ? 16 : 0;
    g_feat[(cb + 2 * t)     * 32 + off + g]     = hout[0];
    g_feat[(cb + 2 * t + 1) * 32 + off + g]     = hout[1];
    g_feat[(cb + 2 * t)     * 32 + off + g + 8] = hout[2];
    g_feat[(cb + 2 * t + 1) * 32 + off + g + 8] = hout[3];
}

// ---------------------------------------------------------------------------
// Kernel 3: out[n,e] = feat[n,:] . lin_w[e,:] + lin_b[e]
// ---------------------------------------------------------------------------
__global__ void __launch_bounds__(256) linear_kernel(
    const float* __restrict__ lw, const float* __restrict__ lb,
    float* __restrict__ out)
{
    const int idx = blockIdx.x * 256 + threadIdx.x;    // 131072 total
    const int n = idx >> 5;
    const int e = idx & 31;
    const float* f = g_feat + n * 32;
    const float* wp = lw + e * 32;
    float acc = lb[e];
#pragma unroll
    for (int k = 0; k < 32; k++) acc = fmaf(f[k], wp[k], acc);
    out[idx] = acc;
}

// ---------------------------------------------------------------------------
extern "C" void kernel_launch(void* const* d_in, const int* in_sizes, int n_in,
                              void* d_out, int out_size)
{
    const float* x      = (const float*)d_in[0];
    const float* c1w    = (const float*)d_in[1];
    const float* c1b    = (const float*)d_in[2];
    const float* b1g    = (const float*)d_in[3];
    const float* b1b    = (const float*)d_in[4];
    const float* b1m    = (const float*)d_in[5];
    const float* b1v    = (const float*)d_in[6];
    const float* c2w    = (const float*)d_in[7];
    const float* c2b    = (const float*)d_in[8];
    const float* b2g    = (const float*)d_in[9];
    const float* b2b    = (const float*)d_in[10];
    const float* b2m    = (const float*)d_in[11];
    const float* b2v    = (const float*)d_in[12];
    const float* wihf   = (const float*)d_in[13];
    const float* whhf   = (const float*)d_in[14];
    const float* bihf   = (const float*)d_in[15];
    const float* bhhf   = (const float*)d_in[16];
    const float* wihr   = (const float*)d_in[17];
    const float* whhr   = (const float*)d_in[18];
    const float* bihr   = (const float*)d_in[19];
    const float* bhhr   = (const float*)d_in[20];
    const float* lw     = (const float*)d_in[21];
    const float* lb     = (const float*)d_in[22];
    float* out = (float*)d_out;

    prep_kernel<<<NCH, 256>>>(x, c1w, c1b, b1g, b1b, b1m, b1v,
                              c2w, c2b, b2g, b2b, b2m, b2v);
    lstm_kernel<<<256, 128>>>(wihf, whhf, bihf, bhhf,
                              wihr, whhr, bihr, bhhr);
    linear_kernel<<<(NCH * 32) / 256, 256>>>(lw, lb, out);
}